// round 1
// baseline (speedup 1.0000x reference)
#include <cuda_runtime.h>

#define NB 4
#define NC 64
#define NN 4096

// Scratch (B,C,N) for Q,K and (B,N,C) for V — static device arrays (no allocs).
__device__ float g_Q[NB * NC * NN];
__device__ float g_K[NB * NC * NN];
__device__ float g_V[NB * NN * NC];

typedef unsigned long long u64;

__device__ __forceinline__ void fma2(u64 &d, u64 a, u64 b) {
    asm("fma.rn.f32x2 %0, %1, %2, %0;" : "+l"(d) : "l"(a), "l"(b));
}
__device__ __forceinline__ void mul2(u64 &d, u64 a) {
    asm("mul.rn.f32x2 %0, %0, %1;" : "+l"(d) : "l"(a));
}
__device__ __forceinline__ u64 pack2(float x, float y) {
    u64 r; asm("mov.b64 %0, {%1, %2};" : "=l"(r) : "f"(x), "f"(y)); return r;
}
__device__ __forceinline__ void unpack2(u64 v, float &x, float &y) {
    asm("mov.b64 {%0, %1}, %2;" : "=f"(x), "=f"(y) : "l"(v));
}

// ---------------------------------------------------------------------------
// QKV projection: q/k -> (B,C,N) layout, v -> (B,N,C) layout.
// Block: (b, 64-wide n tile). 256 threads: co = tid&63, g = tid>>6 (16 n each).
// ---------------------------------------------------------------------------
__global__ __launch_bounds__(256) void qkv_kernel(
    const float* __restrict__ x,
    const float* __restrict__ Wq, const float* __restrict__ bq,
    const float* __restrict__ Wk, const float* __restrict__ bk,
    const float* __restrict__ Wv, const float* __restrict__ bv)
{
    __shared__ float xs[64 * 64];    // [c][n]
    __shared__ float wts[64 * 65];   // W transposed [c][co], pad 65 -> conflict-free

    const int tid = threadIdx.x;
    const int b = blockIdx.y;
    const int n0 = blockIdx.x * 64;

    // Load x tile (coalesced over n)
    for (int idx = tid; idx < 4096; idx += 256) {
        int c = idx >> 6, nn = idx & 63;
        xs[idx] = x[(size_t)(b * 64 + c) * 4096 + n0 + nn];
    }

    const int co = tid & 63;
    const int g  = tid >> 6;
    const float* Ws[3] = {Wq, Wk, Wv};
    const float* bs[3] = {bq, bk, bv};

    for (int m = 0; m < 3; m++) {
        __syncthreads();
        // Load W_m transposed (coalesced read, stride-65 write: conflict-free)
        for (int idx = tid; idx < 4096; idx += 256) {
            wts[(idx & 63) * 65 + (idx >> 6)] = Ws[m][idx];
        }
        __syncthreads();

        float acc[16];
        const float bias = bs[m][co];
        #pragma unroll
        for (int i = 0; i < 16; i++) acc[i] = bias;

        #pragma unroll 4
        for (int c = 0; c < 64; c++) {
            float w = wts[c * 65 + co];
            const float4* xp = (const float4*)(xs + c * 64 + g * 16);
            #pragma unroll
            for (int r = 0; r < 4; r++) {
                float4 xv = xp[r];
                acc[4 * r + 0] += w * xv.x;
                acc[4 * r + 1] += w * xv.y;
                acc[4 * r + 2] += w * xv.z;
                acc[4 * r + 3] += w * xv.w;
            }
        }

        const int nbase = n0 + g * 16;
        if (m < 2) {
            float* dst = (m == 0 ? g_Q : g_K) + (size_t)(b * 64 + co) * 4096 + nbase;
            float4* d4 = (float4*)dst;
            #pragma unroll
            for (int r = 0; r < 4; r++)
                d4[r] = make_float4(acc[4 * r], acc[4 * r + 1], acc[4 * r + 2], acc[4 * r + 3]);
        } else {
            #pragma unroll
            for (int i = 0; i < 16; i++)
                g_V[(size_t)(b * 4096 + nbase + i) * 64 + co] = acc[i];
        }
    }
}

// ---------------------------------------------------------------------------
// Fused flash attention (fp32, f32x2 packed FMA).
// Block: 128 queries. 256 threads as 16(ty) x 16(tx).
// S tile: each thread 8q (8ty..) x 8k ({4tx..4tx+3} U {64+4tx..+3})
// O tile: each thread 8q x 4c ({2tx,2tx+1} U {32+2tx,33+2tx})
// ---------------------------------------------------------------------------
__global__ void __launch_bounds__(256, 1) attn_kernel(float* __restrict__ out)
{
    extern __shared__ float sm[];
    float* sQ = sm;                       // 64 x 256 (each q duplicated as pair)
    float* sK = sm + 64 * 256;            // 64 x 128
    float* sV = sK + 64 * 128;            // 128 x 64
    float* sP = sV + 128 * 64;            // 128 x 128

    const int tid = threadIdx.x;
    const int tx = tid & 15;
    const int ty = tid >> 4;
    const int b  = blockIdx.y;
    const int n0 = blockIdx.x * 128;

    const float* Qg = g_Q + (size_t)b * 64 * 4096;
    const float* Kg = g_K + (size_t)b * 64 * 4096;
    const float* Vg = g_V + (size_t)b * 4096 * 64;

    // Load Q tile, duplicated pairs: sQ[c][2q] = sQ[c][2q+1] = Q[c][n0+q]
    for (int idx = tid; idx < 64 * 128; idx += 256) {
        int c = idx >> 7, q = idx & 127;
        float v = Qg[c * 4096 + n0 + q];
        sQ[c * 256 + 2 * q]     = v;
        sQ[c * 256 + 2 * q + 1] = v;
    }

    u64 o[8][2];
    float m_run[8], l_run[8];
    const float NEG_INF = __int_as_float(0xff800000u);
    #pragma unroll
    for (int i = 0; i < 8; i++) {
        o[i][0] = 0ull; o[i][1] = 0ull;
        m_run[i] = NEG_INF; l_run[i] = 0.0f;
    }

    for (int kt = 0; kt < 32; kt++) {
        __syncthreads();   // prev PV done reading sP/sV
        const int k0 = kt * 128;
        for (int idx = tid; idx < 8192; idx += 256) {
            int c = idx >> 7, k = idx & 127;
            sK[idx] = Kg[c * 4096 + k0 + k];
        }
        for (int idx = tid; idx < 8192; idx += 256) {
            sV[idx] = Vg[(size_t)k0 * 64 + idx];   // contiguous (N,C) chunk
        }
        __syncthreads();

        // ---- S = Q^T K on this tile ----
        u64 acc[8][4];
        #pragma unroll
        for (int i = 0; i < 8; i++)
            #pragma unroll
            for (int j = 0; j < 4; j++) acc[i][j] = 0ull;

        #pragma unroll 4
        for (int c = 0; c < 64; c++) {
            const ulonglong2* qp = (const ulonglong2*)(sQ + c * 256 + 16 * ty);
            ulonglong2 qa = qp[0], qb = qp[1], qc = qp[2], qd = qp[3];
            u64 qq[8] = {qa.x, qa.y, qb.x, qb.y, qc.x, qc.y, qd.x, qd.y};
            const float* krow = sK + c * 128;
            ulonglong2 ka = *(const ulonglong2*)(krow + 4 * tx);
            ulonglong2 kb = *(const ulonglong2*)(krow + 64 + 4 * tx);
            u64 kk[4] = {ka.x, ka.y, kb.x, kb.y};
            #pragma unroll
            for (int i = 0; i < 8; i++) {
                #pragma unroll
                for (int j = 0; j < 4; j++) fma2(acc[i][j], qq[i], kk[j]);
            }
        }

        // ---- online softmax ----
        #pragma unroll
        for (int i = 0; i < 8; i++) {
            float s[8];
            unpack2(acc[i][0], s[0], s[1]);
            unpack2(acc[i][1], s[2], s[3]);
            unpack2(acc[i][2], s[4], s[5]);
            unpack2(acc[i][3], s[6], s[7]);
            float mx = s[0];
            #pragma unroll
            for (int j = 1; j < 8; j++) mx = fmaxf(mx, s[j]);
            #pragma unroll
            for (int off = 8; off >= 1; off >>= 1)
                mx = fmaxf(mx, __shfl_xor_sync(0xffffffffu, mx, off));

            float mnew = fmaxf(m_run[i], mx);
            float alpha = __expf(m_run[i] - mnew);
            m_run[i] = mnew;

            float p[8], sum = 0.0f;
            #pragma unroll
            for (int j = 0; j < 8; j++) { p[j] = __expf(s[j] - mnew); sum += p[j]; }
            #pragma unroll
            for (int off = 8; off >= 1; off >>= 1)
                sum += __shfl_xor_sync(0xffffffffu, sum, off);
            l_run[i] = l_run[i] * alpha + sum;

            u64 ap = pack2(alpha, alpha);
            mul2(o[i][0], ap);
            mul2(o[i][1], ap);

            float* pr = sP + (8 * ty + i) * 128;
            *(float4*)(pr + 4 * tx)      = make_float4(p[0], p[1], p[2], p[3]);
            *(float4*)(pr + 64 + 4 * tx) = make_float4(p[4], p[5], p[6], p[7]);
        }
        __syncthreads();   // sP complete, sV still valid

        // ---- O += P V ----
        const float* pbase = sP + 1024 * ty;   // row 8*ty
        #pragma unroll 2
        for (int k = 0; k < 128; k++) {
            u64 v0 = *(const u64*)(sV + k * 64 + 2 * tx);
            u64 v1 = *(const u64*)(sV + k * 64 + 32 + 2 * tx);
            const float* pc = pbase + k;
            #pragma unroll
            for (int i = 0; i < 8; i++) {
                float pv = pc[i * 128];
                u64 pp = pack2(pv, pv);
                fma2(o[i][0], pp, v0);
                fma2(o[i][1], pp, v1);
            }
        }
    }

    // ---- epilogue: normalize and store (B,C,N) ----
    float* outb = out + (size_t)b * 64 * 4096;
    #pragma unroll
    for (int i = 0; i < 8; i++) {
        float inv = 1.0f / l_run[i];
        u64 iv = pack2(inv, inv);
        mul2(o[i][0], iv);
        mul2(o[i][1], iv);
        float a0, a1, b0, b1;
        unpack2(o[i][0], a0, a1);
        unpack2(o[i][1], b0, b1);
        const int n = n0 + 8 * ty + i;
        const int c0 = 2 * tx;
        outb[(c0)      * 4096 + n] = a0;
        outb[(c0 + 1)  * 4096 + n] = a1;
        outb[(c0 + 32) * 4096 + n] = b0;
        outb[(c0 + 33) * 4096 + n] = b1;
    }
}

extern "C" void kernel_launch(void* const* d_in, const int* in_sizes, int n_in,
                              void* d_out, int out_size)
{
    const float* x  = (const float*)d_in[0];
    const float* Wq = (const float*)d_in[1];
    const float* bq = (const float*)d_in[2];
    const float* Wk = (const float*)d_in[3];
    const float* bk = (const float*)d_in[4];
    const float* Wv = (const float*)d_in[5];
    const float* bv = (const float*)d_in[6];
    float* out = (float*)d_out;

    qkv_kernel<<<dim3(64, NB), 256>>>(x, Wq, bq, Wk, bk, Wv, bv);

    const size_t smem = (size_t)(64 * 256 + 64 * 128 + 128 * 64 + 128 * 128) * sizeof(float);
    cudaFuncSetAttribute(attn_kernel, cudaFuncAttributeMaxDynamicSharedMemorySize, (int)smem);
    attn_kernel<<<dim3(32, NB), 256, smem>>>(out);
}

// round 2
// speedup vs baseline: 1.1547x; 1.1547x over previous
#include <cuda_runtime.h>

#define NB 4
#define NC 64
#define NN 4096

// Scratch (B,C,N) for Q,K and (B,N,C) for V — static device arrays (no allocs).
__device__ float g_Q[NB * NC * NN];
__device__ float g_K[NB * NC * NN];
__device__ float g_V[NB * NN * NC];

typedef unsigned long long u64;

__device__ __forceinline__ void fma2(u64 &d, u64 a, u64 b) {
    asm("fma.rn.f32x2 %0, %1, %2, %0;" : "+l"(d) : "l"(a), "l"(b));
}
__device__ __forceinline__ void mul2(u64 &d, u64 a) {
    asm("mul.rn.f32x2 %0, %0, %1;" : "+l"(d) : "l"(a));
}
__device__ __forceinline__ u64 pack2(float x, float y) {
    u64 r; asm("mov.b64 %0, {%1, %2};" : "=l"(r) : "f"(x), "f"(y)); return r;
}
__device__ __forceinline__ void unpack2(u64 v, float &x, float &y) {
    asm("mov.b64 {%0, %1}, %2;" : "=f"(x), "=f"(y) : "l"(v));
}

// ---------------------------------------------------------------------------
// QKV projection: q/k -> (B,C,N) layout, v -> (B,N,C) layout.
// ---------------------------------------------------------------------------
__global__ __launch_bounds__(256) void qkv_kernel(
    const float* __restrict__ x,
    const float* __restrict__ Wq, const float* __restrict__ bq,
    const float* __restrict__ Wk, const float* __restrict__ bk,
    const float* __restrict__ Wv, const float* __restrict__ bv)
{
    __shared__ float xs[64 * 64];    // [c][n]
    __shared__ float wts[64 * 65];   // W transposed [c][co], pad 65 -> conflict-free

    const int tid = threadIdx.x;
    const int b = blockIdx.y;
    const int n0 = blockIdx.x * 64;

    for (int idx = tid; idx < 4096; idx += 256) {
        int c = idx >> 6, nn = idx & 63;
        xs[idx] = x[(size_t)(b * 64 + c) * 4096 + n0 + nn];
    }

    const int co = tid & 63;
    const int g  = tid >> 6;
    const float* Ws[3] = {Wq, Wk, Wv};
    const float* bs[3] = {bq, bk, bv};

    for (int m = 0; m < 3; m++) {
        __syncthreads();
        for (int idx = tid; idx < 4096; idx += 256) {
            wts[(idx & 63) * 65 + (idx >> 6)] = Ws[m][idx];
        }
        __syncthreads();

        float acc[16];
        const float bias = bs[m][co];
        #pragma unroll
        for (int i = 0; i < 16; i++) acc[i] = bias;

        #pragma unroll 4
        for (int c = 0; c < 64; c++) {
            float w = wts[c * 65 + co];
            const float4* xp = (const float4*)(xs + c * 64 + g * 16);
            #pragma unroll
            for (int r = 0; r < 4; r++) {
                float4 xv = xp[r];
                acc[4 * r + 0] += w * xv.x;
                acc[4 * r + 1] += w * xv.y;
                acc[4 * r + 2] += w * xv.z;
                acc[4 * r + 3] += w * xv.w;
            }
        }

        const int nbase = n0 + g * 16;
        if (m < 2) {
            float* dst = (m == 0 ? g_Q : g_K) + (size_t)(b * 64 + co) * 4096 + nbase;
            float4* d4 = (float4*)dst;
            #pragma unroll
            for (int r = 0; r < 4; r++)
                d4[r] = make_float4(acc[4 * r], acc[4 * r + 1], acc[4 * r + 2], acc[4 * r + 3]);
        } else {
            #pragma unroll
            for (int i = 0; i < 16; i++)
                g_V[(size_t)(b * 4096 + nbase + i) * 64 + co] = acc[i];
        }
    }
}

// ---------------------------------------------------------------------------
// Fused flash attention (fp32, f32x2 packed FMA), 2 CTAs/SM.
// Block: 64 queries, k in 128-wide tiles. 256 threads as 16(ty) x 16(tx).
// S tile: thread = 4q (4ty..) x 8k ({4tx..+3} U {64+4tx..+3})
// O tile: thread = 4q x 4c ({2tx,2tx+1} U {32+2tx,33+2tx})
// smem: sQ 16K + sK 32K + sV 32K + sP 32K = 112KB -> 2 CTAs fit in 228KB.
// ---------------------------------------------------------------------------
__global__ void __launch_bounds__(256, 2) attn_kernel(float* __restrict__ out)
{
    extern __shared__ float sm[];
    float* sQ = sm;                  // 64 x 64   [c][q]
    float* sK = sQ + 64 * 64;        // 64 x 128  [c][k]
    float* sV = sK + 64 * 128;       // 128 x 64  [k][c]
    float* sP = sV + 128 * 64;       // 64 x 128  [q][k]

    const int tid = threadIdx.x;
    const int tx = tid & 15;
    const int ty = tid >> 4;
    const int b  = blockIdx.y;
    const int n0 = blockIdx.x * 64;

    const float* Qg = g_Q + (size_t)b * 64 * 4096;
    const float* Kg = g_K + (size_t)b * 64 * 4096;
    const float* Vg = g_V + (size_t)b * 4096 * 64;

    // Load Q tile [c][q] (coalesced 64-float rows)
    for (int idx = tid; idx < 4096; idx += 256) {
        sQ[idx] = Qg[(idx >> 6) * 4096 + n0 + (idx & 63)];
    }

    u64 o[4][2];
    float m_run[4], l_run[4];
    const float NEG_INF = __int_as_float(0xff800000u);
    #pragma unroll
    for (int i = 0; i < 4; i++) {
        o[i][0] = 0ull; o[i][1] = 0ull;
        m_run[i] = NEG_INF; l_run[i] = 0.0f;
    }

    for (int kt = 0; kt < 32; kt++) {
        __syncthreads();   // prev PV done reading sP/sV
        const int k0 = kt * 128;
        for (int idx = tid; idx < 8192; idx += 256) {
            sK[idx] = Kg[(idx >> 7) * 4096 + k0 + (idx & 127)];
        }
        for (int idx = tid; idx < 8192; idx += 256) {
            sV[idx] = Vg[(size_t)k0 * 64 + idx];   // contiguous (N,C) chunk
        }
        __syncthreads();

        // ---- S = Q^T K on this tile ----
        u64 acc[4][4];
        #pragma unroll
        for (int i = 0; i < 4; i++)
            #pragma unroll
            for (int j = 0; j < 4; j++) acc[i][j] = 0ull;

        #pragma unroll 4
        for (int c = 0; c < 64; c++) {
            float4 qv = *(const float4*)(sQ + c * 64 + 4 * ty);  // warp-broadcast
            u64 qq[4] = {pack2(qv.x, qv.x), pack2(qv.y, qv.y),
                         pack2(qv.z, qv.z), pack2(qv.w, qv.w)};
            const float* krow = sK + c * 128;
            ulonglong2 ka = *(const ulonglong2*)(krow + 4 * tx);
            ulonglong2 kb = *(const ulonglong2*)(krow + 64 + 4 * tx);
            u64 kk[4] = {ka.x, ka.y, kb.x, kb.y};
            #pragma unroll
            for (int i = 0; i < 4; i++) {
                #pragma unroll
                for (int j = 0; j < 4; j++) fma2(acc[i][j], qq[i], kk[j]);
            }
        }

        // ---- online softmax (reduce across 16 tx lanes) ----
        #pragma unroll
        for (int i = 0; i < 4; i++) {
            float s[8];
            unpack2(acc[i][0], s[0], s[1]);
            unpack2(acc[i][1], s[2], s[3]);
            unpack2(acc[i][2], s[4], s[5]);
            unpack2(acc[i][3], s[6], s[7]);
            float mx = s[0];
            #pragma unroll
            for (int j = 1; j < 8; j++) mx = fmaxf(mx, s[j]);
            #pragma unroll
            for (int off = 8; off >= 1; off >>= 1)
                mx = fmaxf(mx, __shfl_xor_sync(0xffffffffu, mx, off));

            float mnew = fmaxf(m_run[i], mx);
            float alpha = __expf(m_run[i] - mnew);
            m_run[i] = mnew;

            float p[8], sum = 0.0f;
            #pragma unroll
            for (int j = 0; j < 8; j++) { p[j] = __expf(s[j] - mnew); sum += p[j]; }
            #pragma unroll
            for (int off = 8; off >= 1; off >>= 1)
                sum += __shfl_xor_sync(0xffffffffu, sum, off);
            l_run[i] = l_run[i] * alpha + sum;

            u64 ap = pack2(alpha, alpha);
            mul2(o[i][0], ap);
            mul2(o[i][1], ap);

            float* pr = sP + (4 * ty + i) * 128;
            *(float4*)(pr + 4 * tx)      = make_float4(p[0], p[1], p[2], p[3]);
            *(float4*)(pr + 64 + 4 * tx) = make_float4(p[4], p[5], p[6], p[7]);
        }
        __syncthreads();   // sP complete, sV still valid

        // ---- O += P V ----
        #pragma unroll 4
        for (int k = 0; k < 128; k++) {
            u64 v0 = *(const u64*)(sV + k * 64 + 2 * tx);
            u64 v1 = *(const u64*)(sV + k * 64 + 32 + 2 * tx);
            #pragma unroll
            for (int i = 0; i < 4; i++) {
                float pv = sP[(4 * ty + i) * 128 + k];   // warp-broadcast
                u64 pp = pack2(pv, pv);
                fma2(o[i][0], pp, v0);
                fma2(o[i][1], pp, v1);
            }
        }
    }

    // ---- epilogue: normalize and store (B,C,N) ----
    float* outb = out + (size_t)b * 64 * 4096;
    #pragma unroll
    for (int i = 0; i < 4; i++) {
        float inv = 1.0f / l_run[i];
        u64 iv = pack2(inv, inv);
        mul2(o[i][0], iv);
        mul2(o[i][1], iv);
        float a0, a1, b0, b1;
        unpack2(o[i][0], a0, a1);
        unpack2(o[i][1], b0, b1);
        const int n = n0 + 4 * ty + i;
        const int c0 = 2 * tx;
        outb[(c0)      * 4096 + n] = a0;
        outb[(c0 + 1)  * 4096 + n] = a1;
        outb[(c0 + 32) * 4096 + n] = b0;
        outb[(c0 + 33) * 4096 + n] = b1;
    }
}

extern "C" void kernel_launch(void* const* d_in, const int* in_sizes, int n_in,
                              void* d_out, int out_size)
{
    const float* x  = (const float*)d_in[0];
    const float* Wq = (const float*)d_in[1];
    const float* bq = (const float*)d_in[2];
    const float* Wk = (const float*)d_in[3];
    const float* bk = (const float*)d_in[4];
    const float* Wv = (const float*)d_in[5];
    const float* bv = (const float*)d_in[6];
    float* out = (float*)d_out;

    qkv_kernel<<<dim3(64, NB), 256>>>(x, Wq, bq, Wk, bk, Wv, bv);

    const size_t smem = (size_t)(64 * 64 + 64 * 128 + 128 * 64 + 64 * 128) * sizeof(float);
    cudaFuncSetAttribute(attn_kernel, cudaFuncAttributeMaxDynamicSharedMemorySize, (int)smem);
    attn_kernel<<<dim3(64, NB), 256, smem>>>(out);
}

// round 3
// speedup vs baseline: 1.1555x; 1.0007x over previous
#include <cuda_runtime.h>

#define NB 4
#define NC 64
#define NN 4096

// Scratch (B,C,N) for Q,K and (B,N,C) for V — static device arrays (no allocs).
__device__ float g_Q[NB * NC * NN];
__device__ float g_K[NB * NC * NN];
__device__ float g_V[NB * NN * NC];

typedef unsigned long long u64;

__device__ __forceinline__ void fma2(u64 &d, u64 a, u64 b) {
    asm("fma.rn.f32x2 %0, %1, %2, %0;" : "+l"(d) : "l"(a), "l"(b));
}
__device__ __forceinline__ void mul2(u64 &d, u64 a) {
    asm("mul.rn.f32x2 %0, %0, %1;" : "+l"(d) : "l"(a));
}
__device__ __forceinline__ u64 pack2(float x, float y) {
    u64 r; asm("mov.b64 %0, {%1, %2};" : "=l"(r) : "f"(x), "f"(y)); return r;
}
__device__ __forceinline__ void unpack2(u64 v, float &x, float &y) {
    asm("mov.b64 {%0, %1}, %2;" : "=f"(x), "=f"(y) : "l"(v));
}

// ---------------------------------------------------------------------------
// QKV projection: q/k -> (B,C,N) layout, v -> (B,N,C) layout.
// ---------------------------------------------------------------------------
__global__ __launch_bounds__(256) void qkv_kernel(
    const float* __restrict__ x,
    const float* __restrict__ Wq, const float* __restrict__ bq,
    const float* __restrict__ Wk, const float* __restrict__ bk,
    const float* __restrict__ Wv, const float* __restrict__ bv)
{
    __shared__ float xs[64 * 64];    // [c][n]
    __shared__ float wts[64 * 65];   // W transposed [c][co], pad 65 -> conflict-free

    const int tid = threadIdx.x;
    const int b = blockIdx.y;
    const int n0 = blockIdx.x * 64;

    for (int idx = tid; idx < 4096; idx += 256) {
        int c = idx >> 6, nn = idx & 63;
        xs[idx] = x[(size_t)(b * 64 + c) * 4096 + n0 + nn];
    }

    const int co = tid & 63;
    const int g  = tid >> 6;
    const float* Ws[3] = {Wq, Wk, Wv};
    const float* bs[3] = {bq, bk, bv};

    for (int m = 0; m < 3; m++) {
        __syncthreads();
        for (int idx = tid; idx < 4096; idx += 256) {
            wts[(idx & 63) * 65 + (idx >> 6)] = Ws[m][idx];
        }
        __syncthreads();

        float acc[16];
        const float bias = bs[m][co];
        #pragma unroll
        for (int i = 0; i < 16; i++) acc[i] = bias;

        #pragma unroll 4
        for (int c = 0; c < 64; c++) {
            float w = wts[c * 65 + co];
            const float4* xp = (const float4*)(xs + c * 64 + g * 16);
            #pragma unroll
            for (int r = 0; r < 4; r++) {
                float4 xv = xp[r];
                acc[4 * r + 0] += w * xv.x;
                acc[4 * r + 1] += w * xv.y;
                acc[4 * r + 2] += w * xv.z;
                acc[4 * r + 3] += w * xv.w;
            }
        }

        const int nbase = n0 + g * 16;
        if (m < 2) {
            float* dst = (m == 0 ? g_Q : g_K) + (size_t)(b * 64 + co) * 4096 + nbase;
            float4* d4 = (float4*)dst;
            #pragma unroll
            for (int r = 0; r < 4; r++)
                d4[r] = make_float4(acc[4 * r], acc[4 * r + 1], acc[4 * r + 2], acc[4 * r + 3]);
        } else {
            #pragma unroll
            for (int i = 0; i < 16; i++)
                g_V[(size_t)(b * 4096 + nbase + i) * 64 + co] = acc[i];
        }
    }
}

// ---------------------------------------------------------------------------
// Fused flash attention (fp32, f32x2 packed FMA), 2 CTAs/SM.
// Block: 64 queries, k in 128-wide tiles. 256 threads as 16(ty) x 16(tx).
// S tile: thread = 4q (4ty..) x 8k ({4tx..+3} U {64+4tx..+3})
// O tile: thread = 4q x 4c ({2tx,2tx+1} U {32+2tx,33+2tx})
// smem: sQ 16K + sK 32K + sV 32K + sP 32K = 112KB -> 2 CTAs fit in 228KB.
// ---------------------------------------------------------------------------
__global__ void __launch_bounds__(256, 2) attn_kernel(float* __restrict__ out)
{
    extern __shared__ float sm[];
    float* sQ = sm;                  // 64 x 64   [c][q]
    float* sK = sQ + 64 * 64;        // 64 x 128  [c][k]
    float* sV = sK + 64 * 128;       // 128 x 64  [k][c]
    float* sP = sV + 128 * 64;       // 64 x 128  [q][k]

    const int tid = threadIdx.x;
    const int tx = tid & 15;
    const int ty = tid >> 4;
    const int b  = blockIdx.y;
    const int n0 = blockIdx.x * 64;

    const float* Qg = g_Q + (size_t)b * 64 * 4096;
    const float* Kg = g_K + (size_t)b * 64 * 4096;
    const float* Vg = g_V + (size_t)b * 4096 * 64;

    // Load Q tile [c][q] (coalesced 64-float rows)
    for (int idx = tid; idx < 4096; idx += 256) {
        sQ[idx] = Qg[(idx >> 6) * 4096 + n0 + (idx & 63)];
    }

    u64 o[4][2];
    float m_run[4], l_run[4];
    const float NEG_INF = __int_as_float(0xff800000u);
    #pragma unroll
    for (int i = 0; i < 4; i++) {
        o[i][0] = 0ull; o[i][1] = 0ull;
        m_run[i] = NEG_INF; l_run[i] = 0.0f;
    }

    for (int kt = 0; kt < 32; kt++) {
        __syncthreads();   // prev PV done reading sP/sV
        const int k0 = kt * 128;
        for (int idx = tid; idx < 8192; idx += 256) {
            sK[idx] = Kg[(idx >> 7) * 4096 + k0 + (idx & 127)];
        }
        for (int idx = tid; idx < 8192; idx += 256) {
            sV[idx] = Vg[(size_t)k0 * 64 + idx];   // contiguous (N,C) chunk
        }
        __syncthreads();

        // ---- S = Q^T K on this tile ----
        u64 acc[4][4];
        #pragma unroll
        for (int i = 0; i < 4; i++)
            #pragma unroll
            for (int j = 0; j < 4; j++) acc[i][j] = 0ull;

        #pragma unroll 4
        for (int c = 0; c < 64; c++) {
            float4 qv = *(const float4*)(sQ + c * 64 + 4 * ty);  // warp-broadcast
            u64 qq[4] = {pack2(qv.x, qv.x), pack2(qv.y, qv.y),
                         pack2(qv.z, qv.z), pack2(qv.w, qv.w)};
            const float* krow = sK + c * 128;
            ulonglong2 ka = *(const ulonglong2*)(krow + 4 * tx);
            ulonglong2 kb = *(const ulonglong2*)(krow + 64 + 4 * tx);
            u64 kk[4] = {ka.x, ka.y, kb.x, kb.y};
            #pragma unroll
            for (int i = 0; i < 4; i++) {
                #pragma unroll
                for (int j = 0; j < 4; j++) fma2(acc[i][j], qq[i], kk[j]);
            }
        }

        // ---- online softmax (reduce across 16 tx lanes) ----
        #pragma unroll
        for (int i = 0; i < 4; i++) {
            float s[8];
            unpack2(acc[i][0], s[0], s[1]);
            unpack2(acc[i][1], s[2], s[3]);
            unpack2(acc[i][2], s[4], s[5]);
            unpack2(acc[i][3], s[6], s[7]);
            float mx = s[0];
            #pragma unroll
            for (int j = 1; j < 8; j++) mx = fmaxf(mx, s[j]);
            #pragma unroll
            for (int off = 8; off >= 1; off >>= 1)
                mx = fmaxf(mx, __shfl_xor_sync(0xffffffffu, mx, off));

            float mnew = fmaxf(m_run[i], mx);
            float alpha = __expf(m_run[i] - mnew);
            m_run[i] = mnew;

            float p[8], sum = 0.0f;
            #pragma unroll
            for (int j = 0; j < 8; j++) { p[j] = __expf(s[j] - mnew); sum += p[j]; }
            #pragma unroll
            for (int off = 8; off >= 1; off >>= 1)
                sum += __shfl_xor_sync(0xffffffffu, sum, off);
            l_run[i] = l_run[i] * alpha + sum;

            u64 ap = pack2(alpha, alpha);
            mul2(o[i][0], ap);
            mul2(o[i][1], ap);

            float* pr = sP + (4 * ty + i) * 128;
            *(float4*)(pr + 4 * tx)      = make_float4(p[0], p[1], p[2], p[3]);
            *(float4*)(pr + 64 + 4 * tx) = make_float4(p[4], p[5], p[6], p[7]);
        }
        __syncthreads();   // sP complete, sV still valid

        // ---- O += P V ----
        #pragma unroll 4
        for (int k = 0; k < 128; k++) {
            u64 v0 = *(const u64*)(sV + k * 64 + 2 * tx);
            u64 v1 = *(const u64*)(sV + k * 64 + 32 + 2 * tx);
            #pragma unroll
            for (int i = 0; i < 4; i++) {
                float pv = sP[(4 * ty + i) * 128 + k];   // warp-broadcast
                u64 pp = pack2(pv, pv);
                fma2(o[i][0], pp, v0);
                fma2(o[i][1], pp, v1);
            }
        }
    }

    // ---- epilogue: normalize and store (B,C,N) ----
    float* outb = out + (size_t)b * 64 * 4096;
    #pragma unroll
    for (int i = 0; i < 4; i++) {
        float inv = 1.0f / l_run[i];
        u64 iv = pack2(inv, inv);
        mul2(o[i][0], iv);
        mul2(o[i][1], iv);
        float a0, a1, b0, b1;
        unpack2(o[i][0], a0, a1);
        unpack2(o[i][1], b0, b1);
        const int n = n0 + 4 * ty + i;
        const int c0 = 2 * tx;
        outb[(c0)      * 4096 + n] = a0;
        outb[(c0 + 1)  * 4096 + n] = a1;
        outb[(c0 + 32) * 4096 + n] = b0;
        outb[(c0 + 33) * 4096 + n] = b1;
    }
}

extern "C" void kernel_launch(void* const* d_in, const int* in_sizes, int n_in,
                              void* d_out, int out_size)
{
    const float* x  = (const float*)d_in[0];
    const float* Wq = (const float*)d_in[1];
    const float* bq = (const float*)d_in[2];
    const float* Wk = (const float*)d_in[3];
    const float* bk = (const float*)d_in[4];
    const float* Wv = (const float*)d_in[5];
    const float* bv = (const float*)d_in[6];
    float* out = (float*)d_out;

    qkv_kernel<<<dim3(64, NB), 256>>>(x, Wq, bq, Wk, bk, Wv, bv);

    const size_t smem = (size_t)(64 * 64 + 64 * 128 + 128 * 64 + 64 * 128) * sizeof(float);
    cudaFuncSetAttribute(attn_kernel, cudaFuncAttributeMaxDynamicSharedMemorySize, (int)smem);
    attn_kernel<<<dim3(64, NB), 256, smem>>>(out);
}